// round 2
// baseline (speedup 1.0000x reference)
#include <cuda_runtime.h>
#include <cuda_bf16.h>
#include <cstdint>
#include <cstdio>

// ---------------- problem constants (fixed by setup_inputs) ----------------
#define S_TOT 2048
#define BATCH 16
#define FEAT  100
#define EMB   512
#define HID   512
#define NOUT  10
#define DEC   1024
#define FF    2048
#define NHEAD 8
#define DHEAD 64
#define SEP   1024
#define TROWS (SEP*BATCH)      // 16384 train rows
#define EROWS ((S_TOT-SEP)*BATCH) // 16384 eval rows (flattened e*B+b)

// ---------------- scratch (device globals; reused across stages) -----------
__device__ float g_bufA[TROWS * EMB];   // train_x  -> later h_eval
__device__ float g_bufB[TROWS * EMB];   // q        -> wo-out -> ffn2-out
__device__ float g_bufC[TROWS * EMB];   // k        -> z
__device__ float g_bufD[TROWS * EMB];   // v        -> out
__device__ float g_bufE[TROWS * EMB];   // attn out (pre-Wo)
__device__ float g_ff  [TROWS * FF];    // ffn hidden
__device__ float g_pool[BATCH * EMB];
__device__ float g_dh  [BATCH * DEC];
__device__ float g_w1  [BATCH * FEAT * HID];
__device__ float g_b1v [BATCH * HID];
__device__ float g_w2  [BATCH * HID * NOUT];
__device__ float g_b2v [BATCH * NOUT];

// ---------------- generic SGEMM 128x128x8, 256 threads, 8x8/thread --------
// A: [M,K] with row stride lda (+ z*aZ), B: [K,N] row-major (+ z*bZ),
// C: row*ldc + col (+ z*cZ).
// EPI: 0 none, 1 +bias, 2 +bias,relu, 3 encoder (+bias + y[row]*yW + yb)
#define BM 128
#define BN 128
#define BKK 8

__device__ __forceinline__ float nanclean(float v) {
    if (v != v) return 0.0f;
    return fminf(fmaxf(v, -3.402823466e38f), 3.402823466e38f);
}

template<int EPI, bool NANC>
__global__ __launch_bounds__(256)
void sgemm_kernel(const float* __restrict__ A, const float* __restrict__ Bm,
                  float* __restrict__ C,
                  int M, int N, int K, int lda, int ldc,
                  const float* __restrict__ bias, int biasZ,
                  const float* __restrict__ yv, const float* __restrict__ yW,
                  const float* __restrict__ yb,
                  long aZ, long bZ, long cZ)
{
    __shared__ float As[BKK][BM];
    __shared__ float Bs[BKK][BN];

    const float* Ab = A + (long)blockIdx.z * aZ;
    const float* Bb = Bm + (long)blockIdx.z * bZ;
    float*       Cb = C + (long)blockIdx.z * cZ;
    const float* biasb = bias ? (bias + (long)blockIdx.z * biasZ) : nullptr;

    const int m0 = blockIdx.y * BM;
    const int n0 = blockIdx.x * BN;
    const int tid = threadIdx.x;
    const int tx = tid & 15;        // 0..15 -> col group
    const int ty = tid >> 4;        // 0..15 -> row group

    const int am = tid >> 1;        // A load: row 0..127
    const int ak = (tid & 1) * 4;   // A load: k 0 or 4
    const int bk = tid >> 5;        // B load: k 0..7
    const int bn = (tid & 31) * 4;  // B load: n

    float acc[8][8];
    #pragma unroll
    for (int i = 0; i < 8; i++)
        #pragma unroll
        for (int j = 0; j < 8; j++) acc[i][j] = 0.0f;

    for (int k0 = 0; k0 < K; k0 += BKK) {
        // ---- load A tile (transposed into As[k][m]) ----
        float4 av;
        if (k0 + BKK <= K) {
            av = *(const float4*)(Ab + (size_t)(m0 + am) * lda + k0 + ak);
        } else {
            const float* ap = Ab + (size_t)(m0 + am) * lda;
            av.x = (k0 + ak + 0 < K) ? ap[k0 + ak + 0] : 0.0f;
            av.y = (k0 + ak + 1 < K) ? ap[k0 + ak + 1] : 0.0f;
            av.z = (k0 + ak + 2 < K) ? ap[k0 + ak + 2] : 0.0f;
            av.w = (k0 + ak + 3 < K) ? ap[k0 + ak + 3] : 0.0f;
        }
        if (NANC) { av.x = nanclean(av.x); av.y = nanclean(av.y);
                    av.z = nanclean(av.z); av.w = nanclean(av.w); }
        As[ak + 0][am] = av.x; As[ak + 1][am] = av.y;
        As[ak + 2][am] = av.z; As[ak + 3][am] = av.w;

        // ---- load B tile ----
        float4 bv2;
        if (k0 + bk < K) {
            bv2 = *(const float4*)(Bb + (size_t)(k0 + bk) * N + n0 + bn);
        } else {
            bv2.x = bv2.y = bv2.z = bv2.w = 0.0f;
        }
        Bs[bk][bn + 0] = bv2.x; Bs[bk][bn + 1] = bv2.y;
        Bs[bk][bn + 2] = bv2.z; Bs[bk][bn + 3] = bv2.w;

        __syncthreads();

        #pragma unroll
        for (int kk = 0; kk < BKK; kk++) {
            float ra[8], rb[8];
            #pragma unroll
            for (int i = 0; i < 8; i++) ra[i] = As[kk][ty * 8 + i];
            #pragma unroll
            for (int j = 0; j < 8; j++) rb[j] = Bs[kk][tx * 8 + j];
            #pragma unroll
            for (int i = 0; i < 8; i++)
                #pragma unroll
                for (int j = 0; j < 8; j++)
                    acc[i][j] += ra[i] * rb[j];
        }
        __syncthreads();
    }

    // ---- epilogue ----
    #pragma unroll
    for (int i = 0; i < 8; i++) {
        const int row = m0 + ty * 8 + i;
        float yval = 0.0f;
        if (EPI == 3) yval = yv[row];
        #pragma unroll
        for (int j = 0; j < 8; j++) {
            const int col = n0 + tx * 8 + j;
            float v = acc[i][j];
            if (EPI == 1) v += biasb[col];
            if (EPI == 2) { v += biasb[col]; v = fmaxf(v, 0.0f); }
            if (EPI == 3) { v += biasb[col] + yval * yW[col] + yb[col]; }
            Cb[(size_t)row * ldc + col] = v;
        }
    }
}

// ---------------- flash attention: per-thread one q row --------------------
// layouts: Q/K/V/O as [T*B, E] with head h at column h*64.
#define STILE 16
__global__ __launch_bounds__(128)
void flash_attn_kernel(const float* __restrict__ Q, const float* __restrict__ K,
                       const float* __restrict__ V, float* __restrict__ O)
{
    __shared__ float Ks[STILE][68];
    __shared__ float Vs[STILE][68];

    const int b = blockIdx.z;
    const int h = blockIdx.y;
    const int t = blockIdx.x * 128 + threadIdx.x;
    const size_t qoff = ((size_t)t * BATCH + b) * EMB + h * DHEAD;

    float q[64], o[64];
    #pragma unroll
    for (int d = 0; d < 64; d += 4) {
        float4 qv = *(const float4*)(Q + qoff + d);
        q[d] = qv.x * 0.125f; q[d+1] = qv.y * 0.125f;
        q[d+2] = qv.z * 0.125f; q[d+3] = qv.w * 0.125f;
        o[d] = 0.f; o[d+1] = 0.f; o[d+2] = 0.f; o[d+3] = 0.f;
    }
    float m = -1e30f, l = 0.0f;

    for (int s0 = 0; s0 < SEP; s0 += STILE) {
        __syncthreads();
        // 16 rows x 64 floats x 2 arrays -> 2 float4 per thread per array
        #pragma unroll
        for (int i = 0; i < 2; i++) {
            int idx = threadIdx.x + i * 128;           // 0..255 float4 units
            int r = idx >> 4;
            int d4 = (idx & 15) << 2;
            size_t off = ((size_t)(s0 + r) * BATCH + b) * EMB + h * DHEAD + d4;
            float4 kv = *(const float4*)(K + off);
            Ks[r][d4] = kv.x; Ks[r][d4+1] = kv.y; Ks[r][d4+2] = kv.z; Ks[r][d4+3] = kv.w;
            float4 vv = *(const float4*)(V + off);
            Vs[r][d4] = vv.x; Vs[r][d4+1] = vv.y; Vs[r][d4+2] = vv.z; Vs[r][d4+3] = vv.w;
        }
        __syncthreads();

        float sc[STILE];
        float tmax = -1e30f;
        #pragma unroll
        for (int s = 0; s < STILE; s++) {
            float accd = 0.0f;
            #pragma unroll
            for (int d = 0; d < 64; d++) accd += q[d] * Ks[s][d];
            sc[s] = accd;
            tmax = fmaxf(tmax, accd);
        }
        const float mnew = fmaxf(m, tmax);
        const float corr = __expf(m - mnew);
        l *= corr;
        #pragma unroll
        for (int d = 0; d < 64; d++) o[d] *= corr;
        #pragma unroll
        for (int s = 0; s < STILE; s++) {
            const float p = __expf(sc[s] - mnew);
            l += p;
            #pragma unroll
            for (int d = 0; d < 64; d++) o[d] += p * Vs[s][d];
        }
        m = mnew;
    }

    const float inv = 1.0f / l;
    #pragma unroll
    for (int d = 0; d < 64; d++) O[qoff + d] = o[d] * inv;
}

// ---------------- fused residual add + LayerNorm (E=512) -------------------
__global__ __launch_bounds__(256)
void ln_add_kernel(const float* __restrict__ A, const float* __restrict__ B,
                   const float* __restrict__ g, const float* __restrict__ be,
                   float* __restrict__ out)
{
    __shared__ float red[16];
    const int row = blockIdx.x, tid = threadIdx.x;
    const size_t base = (size_t)row * EMB;
    float x0 = A[base + tid] + B[base + tid];
    float x1 = A[base + tid + 256] + B[base + tid + 256];

    float s = x0 + x1;
    #pragma unroll
    for (int off = 16; off > 0; off >>= 1) s += __shfl_down_sync(0xffffffffu, s, off);
    if ((tid & 31) == 0) red[tid >> 5] = s;
    __syncthreads();
    if (tid < 32) {
        float v = (tid < 8) ? red[tid] : 0.0f;
        #pragma unroll
        for (int off = 4; off > 0; off >>= 1) v += __shfl_down_sync(0xffffffffu, v, off);
        if (tid == 0) red[8] = v;
    }
    __syncthreads();
    const float mean = red[8] * (1.0f / 512.0f);
    const float d0 = x0 - mean, d1 = x1 - mean;

    float sq = d0 * d0 + d1 * d1;
    #pragma unroll
    for (int off = 16; off > 0; off >>= 1) sq += __shfl_down_sync(0xffffffffu, sq, off);
    if ((tid & 31) == 0) red[tid >> 5] = sq;
    __syncthreads();
    if (tid < 32) {
        float v = (tid < 8) ? red[tid] : 0.0f;
        #pragma unroll
        for (int off = 4; off > 0; off >>= 1) v += __shfl_down_sync(0xffffffffu, v, off);
        if (tid == 0) red[9] = v;
    }
    __syncthreads();
    const float var = red[9] * (1.0f / 512.0f);
    const float r = rsqrtf(var + 1e-5f);
    out[base + tid]       = d0 * r * g[tid]       + be[tid];
    out[base + tid + 256] = d1 * r * g[tid + 256] + be[tid + 256];
}

// ---------------- mean pool over train tokens ------------------------------
__global__ void pool_kernel(const float* __restrict__ X, float* __restrict__ P)
{
    const int b = blockIdx.x;
    const int e = threadIdx.x;  // 512 threads
    float s = 0.0f;
    for (int t = 0; t < SEP; t++)
        s += X[((size_t)t * BATCH + b) * EMB + e];
    P[b * EMB + e] = s * (1.0f / (float)SEP);
}

// ---------------- small-M (16) GEMM: C[16,N] = A[16,K] @ B[K,N] ------------
// EPI: 0 none, 2 +bias,relu
template<int EPI>
__global__ __launch_bounds__(128)
void gemm16_kernel(const float* __restrict__ A, const float* __restrict__ B,
                   const float* __restrict__ bias, float* __restrict__ C,
                   int N, int K)
{
    __shared__ float As[16][256];
    const int n = blockIdx.x * 128 + threadIdx.x;
    float acc[16];
    #pragma unroll
    for (int mm = 0; mm < 16; mm++) acc[mm] = 0.0f;

    for (int k0 = 0; k0 < K; k0 += 256) {
        for (int idx = threadIdx.x; idx < 16 * 256; idx += 128) {
            const int mm = idx >> 8, kk = idx & 255;
            As[mm][kk] = A[(size_t)mm * K + k0 + kk];
        }
        __syncthreads();
        if (n < N) {
            for (int kk = 0; kk < 256; kk += 4) {
                float bv0 = B[(size_t)(k0 + kk + 0) * N + n];
                float bv1 = B[(size_t)(k0 + kk + 1) * N + n];
                float bv2 = B[(size_t)(k0 + kk + 2) * N + n];
                float bv3 = B[(size_t)(k0 + kk + 3) * N + n];
                #pragma unroll
                for (int mm = 0; mm < 16; mm++) {
                    float4 a4 = *(const float4*)&As[mm][kk];
                    acc[mm] += a4.x * bv0 + a4.y * bv1 + a4.z * bv2 + a4.w * bv3;
                }
            }
        }
        __syncthreads();
    }
    if (n < N) {
        #pragma unroll
        for (int mm = 0; mm < 16; mm++) {
            float v = acc[mm];
            if (EPI == 2) { v += bias[n]; v = fmaxf(v, 0.0f); }
            C[(size_t)mm * N + n] = v;
        }
    }
}

// ---------------- eval second matmul: out = H @ w2[b] + b2[b] --------------
// H: [e*B+b, 512], w2: [B][512][10], out: [e*B+b][10]
__global__ __launch_bounds__(320)
void eval2_kernel(const float* __restrict__ H, const float* __restrict__ W2,
                  const float* __restrict__ B2, float* __restrict__ out)
{
    __shared__ float hs[32][132];
    __shared__ float w2s[128][10];
    const int b  = blockIdx.y;
    const int e0 = blockIdx.x * 32;
    const int tid = threadIdx.x;
    const int i = tid / 10;   // e row within tile (0..31)
    const int o = tid % 10;
    float acc = 0.0f;

    for (int k0 = 0; k0 < HID; k0 += 128) {
        for (int idx = tid; idx < 32 * 128; idx += 320) {
            const int r = idx >> 7, kk = idx & 127;
            hs[r][kk] = H[((size_t)(e0 + r) * BATCH + b) * HID + k0 + kk];
        }
        for (int idx = tid; idx < 128 * 10; idx += 320) {
            w2s[idx / 10][idx % 10] =
                W2[(size_t)b * (HID * NOUT) + (size_t)(k0 + idx / 10) * NOUT + idx % 10];
        }
        __syncthreads();
        #pragma unroll 8
        for (int kk = 0; kk < 128; kk++)
            acc += hs[i][kk] * w2s[kk][o];
        __syncthreads();
    }
    out[((size_t)(e0 + i) * BATCH + b) * NOUT + o] = acc + B2[b * NOUT + o];
}

// ---------------- host launcher --------------------------------------------
static float* sym(const void* symbol) {
    void* p = nullptr;
    cudaGetSymbolAddress(&p, symbol);
    return (float*)p;
}

extern "C" void kernel_launch(void* const* d_in, const int* in_sizes, int n_in,
                              void* d_out, int out_size)
{
    const float* x       = (const float*)d_in[0];
    const float* y       = (const float*)d_in[1];
    const float* enc_W   = (const float*)d_in[2];
    const float* enc_b   = (const float*)d_in[3];
    const float* yenc_W  = (const float*)d_in[4];
    const float* yenc_b  = (const float*)d_in[5];
    const float* Wq      = (const float*)d_in[6];
    const float* Wk      = (const float*)d_in[7];
    const float* Wv      = (const float*)d_in[8];
    const float* Wo      = (const float*)d_in[9];
    const float* ln1_g   = (const float*)d_in[10];
    const float* ln1_b   = (const float*)d_in[11];
    const float* ln2_g   = (const float*)d_in[12];
    const float* ln2_b   = (const float*)d_in[13];
    const float* ffn_W1  = (const float*)d_in[14];
    const float* ffn_b1  = (const float*)d_in[15];
    const float* ffn_W2  = (const float*)d_in[16];
    const float* ffn_b2  = (const float*)d_in[17];
    const float* dec_W   = (const float*)d_in[18];
    const float* dec_b   = (const float*)d_in[19];
    const float* hw1     = (const float*)d_in[20];
    const float* hb1     = (const float*)d_in[21];
    const float* hw2     = (const float*)d_in[22];
    const float* hb2     = (const float*)d_in[23];
    // d_in[24] = single_eval_pos (fixed at 1024 by the dataset)

    float* bufA = sym(g_bufA);
    float* bufB = sym(g_bufB);
    float* bufC = sym(g_bufC);
    float* bufD = sym(g_bufD);
    float* bufE = sym(g_bufE);
    float* ff   = sym(g_ff);
    float* pool = sym(g_pool);
    float* dh   = sym(g_dh);
    float* w1   = sym(g_w1);
    float* b1v  = sym(g_b1v);
    float* w2   = sym(g_w2);
    float* b2v  = sym(g_b2v);
    float* out  = (float*)d_out;

    // 1) encoder: train_x = x[:sep] @ enc_W + enc_b + y*yenc_W + yenc_b
    sgemm_kernel<3, false><<<dim3(EMB/128, TROWS/128, 1), 256>>>(
        x, enc_W, bufA, TROWS, EMB, FEAT, FEAT, EMB,
        enc_b, 0, y, yenc_W, yenc_b, 0, 0, 0);

    // 2) q, k, v
    sgemm_kernel<0, false><<<dim3(EMB/128, TROWS/128, 1), 256>>>(
        bufA, Wq, bufB, TROWS, EMB, EMB, EMB, EMB,
        nullptr, 0, nullptr, nullptr, nullptr, 0, 0, 0);
    sgemm_kernel<0, false><<<dim3(EMB/128, TROWS/128, 1), 256>>>(
        bufA, Wk, bufC, TROWS, EMB, EMB, EMB, EMB,
        nullptr, 0, nullptr, nullptr, nullptr, 0, 0, 0);
    sgemm_kernel<0, false><<<dim3(EMB/128, TROWS/128, 1), 256>>>(
        bufA, Wv, bufD, TROWS, EMB, EMB, EMB, EMB,
        nullptr, 0, nullptr, nullptr, nullptr, 0, 0, 0);

    // 3) flash attention -> bufE
    flash_attn_kernel<<<dim3(SEP/128, NHEAD, BATCH), 128>>>(bufB, bufC, bufD, bufE);

    // 4) output projection (no bias) -> bufB
    sgemm_kernel<0, false><<<dim3(EMB/128, TROWS/128, 1), 256>>>(
        bufE, Wo, bufB, TROWS, EMB, EMB, EMB, EMB,
        nullptr, 0, nullptr, nullptr, nullptr, 0, 0, 0);

    // 5) z = LN(train_x + ao) -> bufC
    ln_add_kernel<<<TROWS, 256>>>(bufB, bufA, ln1_g, ln1_b, bufC);

    // 6) ffn hidden = relu(z @ W1 + b1)
    sgemm_kernel<2, false><<<dim3(FF/128, TROWS/128, 1), 256>>>(
        bufC, ffn_W1, ff, TROWS, FF, EMB, EMB, FF,
        ffn_b1, 0, nullptr, nullptr, nullptr, 0, 0, 0);

    // 7) ffn out = hidden @ W2 + b2 -> bufB
    sgemm_kernel<1, false><<<dim3(EMB/128, TROWS/128, 1), 256>>>(
        ff, ffn_W2, bufB, TROWS, EMB, FF, FF, EMB,
        ffn_b2, 0, nullptr, nullptr, nullptr, 0, 0, 0);

    // 8) out = LN(z + ffn) -> bufD
    ln_add_kernel<<<TROWS, 256>>>(bufB, bufC, ln2_g, ln2_b, bufD);

    // 9) pooled mean over train tokens
    pool_kernel<<<BATCH, EMB>>>(bufD, pool);

    // 10) dh = relu(pooled @ dec_W + dec_b)
    gemm16_kernel<2><<<DEC/128, 128>>>(pool, dec_W, dec_b, dh, DEC, EMB);

    // 11) hypernetwork heads (no bias)
    gemm16_kernel<0><<<(FEAT*HID)/128, 128>>>(dh, hw1, nullptr, w1, FEAT*HID, DEC);
    gemm16_kernel<0><<<HID/128, 128>>>(dh, hb1, nullptr, b1v, HID, DEC);
    gemm16_kernel<0><<<(HID*NOUT)/128, 128>>>(dh, hw2, nullptr, w2, HID*NOUT, DEC);
    gemm16_kernel<0><<<1, 128>>>(dh, hb2, nullptr, b2v, NOUT, DEC);

    // 12) eval layer 1: h = relu(nan_to_num(x_eval) @ w1[b] + b1[b]) -> bufA
    //     A rows strided by B*F, per-batch offset b*F; C rows strided by B*HID
    sgemm_kernel<2, true><<<dim3(HID/128, (S_TOT-SEP)/128, BATCH), 256>>>(
        x + (size_t)SEP * BATCH * FEAT, w1, bufA,
        S_TOT-SEP, HID, FEAT, BATCH*FEAT, BATCH*HID,
        b1v, HID, nullptr, nullptr, nullptr,
        (long)FEAT, (long)FEAT*HID, (long)HID);

    // 13) eval layer 2: out = h @ w2[b] + b2[b]
    eval2_kernel<<<dim3((S_TOT-SEP)/32, BATCH), 320>>>(bufA, w2, b2v, out);
}

// round 8
// speedup vs baseline: 2.0441x; 2.0441x over previous
#include <cuda_runtime.h>
#include <cuda_bf16.h>
#include <cstdint>

#define S_TOT 2048
#define BATCH 16
#define FEAT  100
#define EMB   512
#define HID   512
#define NOUT  10
#define DEC   1024
#define FF    2048
#define SEP   1024
#define TROWS (SEP*BATCH)
#define ZTOT  128

typedef __nv_bfloat16 bf16;

__device__ __forceinline__ uint32_t s2u(const void* p) {
    uint32_t a; asm("{ .reg .u64 t; cvta.to.shared.u64 t, %1; cvt.u32.u64 %0, t; }":"=r"(a):"l"(p)); return a;
}
__device__ __forceinline__ void ldsm_x4(uint32_t addr, uint32_t* r){
    asm volatile("ldmatrix.sync.aligned.m8n8.x4.shared.b16 {%0,%1,%2,%3}, [%4];"
        : "=r"(r[0]),"=r"(r[1]),"=r"(r[2]),"=r"(r[3]) : "r"(addr));
}
__device__ __forceinline__ void ldsm_x2(uint32_t addr, uint32_t* r){
    asm volatile("ldmatrix.sync.aligned.m8n8.x2.shared.b16 {%0,%1}, [%2];"
        : "=r"(r[0]),"=r"(r[1]) : "r"(addr));
}
#define MMA(c, a, b) asm volatile( \
    "mma.sync.aligned.m16n8k16.row.col.f32.bf16.bf16.f32 {%0,%1,%2,%3},{%4,%5,%6,%7},{%8,%9},{%0,%1,%2,%3};" \
    : "+f"((c)[0]),"+f"((c)[1]),"+f"((c)[2]),"+f"((c)[3]) \
    : "r"((a)[0]),"r"((a)[1]),"r"((a)[2]),"r"((a)[3]),"r"((b)[0]),"r"((b)[1]))

// ---------------- scratch: each array is its OWN symbol (interior symbol
// indexing like g_w[1] breaks cudaGetSymbolAddress -> nullptr -> crash) ----
#define AL __align__(128)
__device__ AL float g_bufA[TROWS*EMB];
__device__ AL float g_bufB[TROWS*EMB];
__device__ AL float g_bufC[TROWS*EMB];
__device__ AL float g_bufD[TROWS*EMB];
__device__ AL bf16 g_xh[TROWS*EMB], g_xl[TROWS*EMB];
__device__ AL bf16 g_wqth[EMB*EMB], g_wqtl[EMB*EMB];
__device__ AL bf16 g_wkth[EMB*EMB], g_wktl[EMB*EMB];
__device__ AL bf16 g_wvth[EMB*EMB], g_wvtl[EMB*EMB];
__device__ AL bf16 g_woth[EMB*EMB], g_wotl[EMB*EMB];
__device__ AL bf16 g_w1th[EMB*FF],  g_w1tl[EMB*FF];
__device__ AL bf16 g_w2th[FF*EMB],  g_w2tl[FF*EMB];
__device__ AL bf16 g_qh[ZTOT*SEP*64], g_ql[ZTOT*SEP*64];
__device__ AL bf16 g_kh[ZTOT*SEP*64], g_kl[ZTOT*SEP*64];
__device__ AL bf16 g_vth[ZTOT*64*SEP], g_vtl[ZTOT*64*SEP];
__device__ AL float g_S[(size_t)ZTOT*SEP*SEP];
__device__ AL bf16 g_Ph[(size_t)ZTOT*SEP*SEP], g_Pl[(size_t)ZTOT*SEP*SEP];
__device__ AL float g_oz[ZTOT*SEP*64];
__device__ AL bf16 g_aoh[TROWS*EMB], g_aol[TROWS*EMB];
__device__ AL bf16 g_ffh[TROWS*FF], g_ffl[TROWS*FF];
__device__ AL float g_pool[BATCH*EMB];
__device__ AL float g_dh[BATCH*DEC];
__device__ AL float g_w1[BATCH*FEAT*HID];
__device__ AL float g_b1v[BATCH*HID];
__device__ AL float g_w2[BATCH*HID*NOUT];
__device__ AL float g_b2v[BATCH*NOUT];

__device__ __forceinline__ void splitb(float v, bf16& h, bf16& l){
    h = __float2bfloat16_rn(v);
    l = __float2bfloat16_rn(v - __bfloat162float(h));
}
__device__ __forceinline__ uint32_t pk(bf16 a, bf16 b){
    return ((uint32_t)__bfloat16_as_ushort(b)<<16)|__bfloat16_as_ushort(a);
}

// ============ bf16x3 MMA GEMM: D = A@B^T; A[m,K], B[n,K] K-major hi/lo ============
// 128 x BNt tile, BK=32, 256 threads (8 warps @ 64 x BNt/4), z-batched.
// STATIC shared (<=40KB). EPI: 0 none, 1 +bias, 2 +bias&relu.
// OUT: 0 fp32->C, 1 hi/lo bf16->Ch/Cl
template<int BNt, int EPI, int OUT>
__global__ __launch_bounds__(256)
void tc_gemm(const bf16* __restrict__ Ah, const bf16* __restrict__ Al,
             const bf16* __restrict__ Bh, const bf16* __restrict__ Bl,
             float* __restrict__ C, bf16* __restrict__ Ch, bf16* __restrict__ Cl,
             const float* __restrict__ bias, int K, int ldc,
             long aZ, long bZ, long cZ)
{
    constexpr int WN = BNt/4;
    constexpr int NF = WN/8;
    constexpr int RS = 80;   // 64B data + 16B pad per 32-element k-chunk row
    __shared__ __align__(16) char sA[2][128*RS];
    __shared__ __align__(16) char sB[2][BNt*RS];

    const int tid = threadIdx.x;
    const int lane = tid & 31, w = tid >> 5;
    const int wm = w & 1, wn = w >> 1;
    const int m0 = blockIdx.y*128, n0 = blockIdx.x*BNt, z = blockIdx.z;
    const uint32_t sa0 = s2u(sA[0]), sa1 = s2u(sA[1]);
    const uint32_t sb0 = s2u(sB[0]), sb1 = s2u(sB[1]);

    const bf16* aH = Ah + (size_t)z*aZ;  const bf16* aL = Al + (size_t)z*aZ;
    const bf16* bH = Bh + (size_t)z*bZ;  const bf16* bL = Bl + (size_t)z*bZ;

    float acc[4][NF][4];
    #pragma unroll
    for (int i = 0; i < 4; i++) {
        #pragma unroll
        for (int j = 0; j < NF; j++) {
            #pragma unroll
            for (int q = 0; q < 4; q++) acc[i][j][q] = 0.0f;
        }
    }

    for (int k0 = 0; k0 < K; k0 += 32) {
        #pragma unroll
        for (int i = 0; i < 2; i++) {
            const int idx = tid + i*256;
            const int r = idx >> 2, cc = idx & 3;
            const size_t g = (size_t)(m0+r)*K + k0 + cc*8;
            *(uint4*)(sA[0] + r*RS + cc*16) = *(const uint4*)(aH + g);
            *(uint4*)(sA[1] + r*RS + cc*16) = *(const uint4*)(aL + g);
        }
        #pragma unroll
        for (int i = 0; i < BNt/64; i++) {
            const int idx = tid + i*256;
            const int r = idx >> 2, cc = idx & 3;
            const size_t g = (size_t)(n0+r)*K + k0 + cc*8;
            *(uint4*)(sB[0] + r*RS + cc*16) = *(const uint4*)(bH + g);
            *(uint4*)(sB[1] + r*RS + cc*16) = *(const uint4*)(bL + g);
        }
        __syncthreads();

        #pragma unroll
        for (int ks = 0; ks < 2; ks++) {
            uint32_t afh[4][4], afl[4][4], bfh[NF][2], bfl[NF][2];
            #pragma unroll
            for (int mf = 0; mf < 4; mf++) {
                const uint32_t ad = (uint32_t)((wm*64 + mf*16 + (lane&15))*RS
                                               + ks*32 + ((lane>>4)<<4));
                ldsm_x4(sa0 + ad, afh[mf]);
                ldsm_x4(sa1 + ad, afl[mf]);
            }
            #pragma unroll
            for (int nf = 0; nf < NF; nf++) {
                const uint32_t bd = (uint32_t)((wn*WN + nf*8 + (lane&7))*RS
                                               + ks*32 + (((lane>>3)&1)<<4));
                ldsm_x2(sb0 + bd, bfh[nf]);
                ldsm_x2(sb1 + bd, bfl[nf]);
            }
            #pragma unroll
            for (int mf = 0; mf < 4; mf++) {
                #pragma unroll
                for (int nf = 0; nf < NF; nf++) {
                    MMA(acc[mf][nf], afh[mf], bfh[nf]);
                    MMA(acc[mf][nf], afh[mf], bfl[nf]);
                    MMA(acc[mf][nf], afl[mf], bfh[nf]);
                }
            }
        }
        __syncthreads();
    }

    #pragma unroll
    for (int mf = 0; mf < 4; mf++) {
        const int grow = m0 + wm*64 + mf*16 + (lane>>2);
        #pragma unroll
        for (int nf = 0; nf < NF; nf++) {
            const int gc = n0 + wn*WN + nf*8 + 2*(lane&3);
            float b0v = 0.f, b1v = 0.f;
            if (EPI >= 1) { b0v = bias[gc]; b1v = bias[gc+1]; }
            #pragma unroll
            for (int half = 0; half < 2; half++) {
                float v0 = acc[mf][nf][half*2+0] + b0v;
                float v1 = acc[mf][nf][half*2+1] + b1v;
                if (EPI == 2) { v0 = fmaxf(v0, 0.f); v1 = fmaxf(v1, 0.f); }
                const size_t off = (size_t)z*cZ + (size_t)(grow + half*8)*ldc + gc;
                if (OUT == 0) {
                    *(float2*)(C + off) = make_float2(v0, v1);
                } else {
                    bf16 h0,h1,l0,l1;
                    splitb(v0,h0,l0); splitb(v1,h1,l1);
                    *(uint32_t*)(Ch + off) = pk(h0,h1);
                    *(uint32_t*)(Cl + off) = pk(l0,l1);
                }
            }
        }
    }
}

// ============ converts / reshapes ============
__global__ __launch_bounds__(256)
void convert_hilo(const float* __restrict__ X, bf16* __restrict__ H, bf16* __restrict__ L){
    const int i = blockIdx.x*256 + threadIdx.x;
    float4 v = ((const float4*)X)[i];
    bf16 h0,h1,h2,h3,l0,l1,l2,l3;
    splitb(v.x,h0,l0); splitb(v.y,h1,l1); splitb(v.z,h2,l2); splitb(v.w,h3,l3);
    ((uint2*)H)[i] = make_uint2(pk(h0,h1), pk(h2,h3));
    ((uint2*)L)[i] = make_uint2(pk(l0,l1), pk(l2,l3));
}

// W [Kd,Nd] fp32 -> Th/Tl [Nd,Kd] bf16
__global__ void tconv(const float* __restrict__ W, bf16* __restrict__ Th, bf16* __restrict__ Tl,
                      int Kd, int Nd){
    __shared__ float s[32][33];
    const int n0 = blockIdx.x*32, k0 = blockIdx.y*32;
    const int tx = threadIdx.x, ty = threadIdx.y;
    #pragma unroll
    for (int j = 0; j < 4; j++)
        s[ty+j*8][tx] = W[(size_t)(k0+ty+j*8)*Nd + n0+tx];
    __syncthreads();
    #pragma unroll
    for (int j = 0; j < 4; j++) {
        bf16 h,l; splitb(s[tx][ty+j*8], h, l);
        const size_t o = (size_t)(n0+ty+j*8)*Kd + k0+tx;
        Th[o]=h; Tl[o]=l;
    }
}

// X [t*16+b, 512] fp32 -> [z=(b*8+h), t, d] bf16 hi/lo, scaled
__global__ __launch_bounds__(256)
void reshape_qk(const float* __restrict__ X, bf16* __restrict__ H, bf16* __restrict__ L, float sc){
    const int idx = blockIdx.x*256 + threadIdx.x;
    const int d = idx&63, t = (idx>>6)&1023, zz = idx>>16, hh = zz&7, b = zz>>3;
    bf16 h,l; splitb(X[((size_t)(t*16+b)<<9) + (hh<<6) + d]*sc, h, l);
    H[idx]=h; L[idx]=l;
}

// V [t*16+b, 512] fp32 -> Vt [z, d, t] hi/lo
__global__ void reshape_vT(const float* __restrict__ V, bf16* __restrict__ H, bf16* __restrict__ L){
    __shared__ float s[32][33];
    const int z = blockIdx.y, hh = z&7, b = z>>3;
    const int t0 = (blockIdx.x&31)*32, d0 = (blockIdx.x>>5)*32;
    const int tx = threadIdx.x, ty = threadIdx.y;
    #pragma unroll
    for (int j = 0; j < 4; j++)
        s[ty+j*8][tx] = V[((size_t)((t0+ty+j*8)*16+b)<<9) + (hh<<6) + d0+tx];
    __syncthreads();
    #pragma unroll
    for (int j = 0; j < 4; j++) {
        bf16 h,l; splitb(s[tx][ty+j*8], h, l);
        const size_t o = ((size_t)z*64 + d0+ty+j*8)*1024 + t0+tx;
        H[o]=h; L[o]=l;
    }
}

// Oz [z,t,64] fp32 -> [t*16+b, 512] hi/lo
__global__ __launch_bounds__(256)
void reshape_ao(const float* __restrict__ Oz, bf16* __restrict__ H, bf16* __restrict__ L){
    const int idx = blockIdx.x*256 + threadIdx.x;
    const int d = idx&63, hh = (idx>>6)&7, b = (idx>>9)&15, t = idx>>13;
    bf16 h,l; splitb(Oz[(((size_t)(b*8+hh)*1024 + t)<<6) + d], h, l);
    H[idx]=h; L[idx]=l;
}

__device__ __forceinline__ float fexp(float x){
    x = fmaxf(x, -80.0f);
    float y = x * 1.442695041f;
    int n = __float2int_rn(y);
    float f = y - (float)n;
    float p = 0.00133335581f;
    p = fmaf(p,f,0.00961812911f); p = fmaf(p,f,0.0555041087f);
    p = fmaf(p,f,0.240226507f);   p = fmaf(p,f,0.693147182f);
    p = fmaf(p,f,1.0f);
    return p * __int_as_float((n+127)<<23);
}

__global__ __launch_bounds__(256)
void softmax_hilo(const float* __restrict__ S, bf16* __restrict__ Ph, bf16* __restrict__ Pl){
    __shared__ float red[8];
    const size_t row = blockIdx.x;
    const int tid = threadIdx.x;
    float4 v = ((const float4*)(S + row*1024))[tid];
    float4 e = make_float4(fexp(v.x), fexp(v.y), fexp(v.z), fexp(v.w));
    float s = e.x+e.y+e.z+e.w;
    #pragma unroll
    for (int o = 16; o; o >>= 1) s += __shfl_xor_sync(~0u, s, o);
    if ((tid&31)==0) red[tid>>5] = s;
    __syncthreads();
    if (tid < 32) {
        float t = (tid<8) ? red[tid] : 0.0f;
        #pragma unroll
        for (int o = 4; o; o >>= 1) t += __shfl_xor_sync(~0u, t, o);
        if (tid==0) red[0] = t;
    }
    __syncthreads();
    const float inv = 1.0f/red[0];
    bf16 h0,h1,h2,h3,l0,l1,l2,l3;
    splitb(e.x*inv,h0,l0); splitb(e.y*inv,h1,l1); splitb(e.z*inv,h2,l2); splitb(e.w*inv,h3,l3);
    ((uint2*)Ph)[row*256+tid] = make_uint2(pk(h0,h1), pk(h2,h3));
    ((uint2*)Pl)[row*256+tid] = make_uint2(pk(l0,l1), pk(l2,l3));
}

// ============ fp32 leftovers (R1-proven) ============
__device__ __forceinline__ float nanclean(float v){
    if (v != v) return 0.0f;
    return fminf(fmaxf(v, -3.402823466e38f), 3.402823466e38f);
}

template<int EPI, bool NANC>
__global__ __launch_bounds__(256)
void sgemm_kernel(const float* __restrict__ A, const float* __restrict__ Bm, float* __restrict__ C,
                  int M, int N, int K, int lda, int ldc,
                  const float* __restrict__ bias, int biasZ,
                  const float* __restrict__ yv, const float* __restrict__ yW, const float* __restrict__ yb,
                  long aZ, long bZ, long cZ)
{
    __shared__ float As[8][128];
    __shared__ float Bs[8][128];
    const float* Ab = A + (long)blockIdx.z*aZ;
    const float* Bb = Bm + (long)blockIdx.z*bZ;
    float* Cb = C + (long)blockIdx.z*cZ;
    const float* biasb = bias ? (bias + (long)blockIdx.z*biasZ) : nullptr;
    const int m0 = blockIdx.y*128, n0 = blockIdx.x*128, tid = threadIdx.x;
    const int tx = tid&15, ty = tid>>4;
    const int am = tid>>1, ak = (tid&1)*4, bk = tid>>5, bn = (tid&31)*4;
    float acc[8][8];
    #pragma unroll
    for (int i = 0; i < 8; i++) {
        #pragma unroll
        for (int j = 0; j < 8; j++) acc[i][j] = 0.0f;
    }
    for (int k0 = 0; k0 < K; k0 += 8) {
        float4 av;
        if (k0 + 8 <= K) {
            av = *(const float4*)(Ab + (size_t)(m0+am)*lda + k0+ak);
        } else {
            const float* ap = Ab + (size_t)(m0+am)*lda;
            av.x = (k0+ak+0<K)?ap[k0+ak+0]:0.f; av.y = (k0+ak+1<K)?ap[k0+ak+1]:0.f;
            av.z = (k0+ak+2<K)?ap[k0+ak+2]:0.f; av.w = (k0+ak+3<K)?ap[k0+ak+3]:0.f;
        }
        if (NANC){ av.x=nanclean(av.x); av.y=nanclean(av.y); av.z=nanclean(av.z); av.w=nanclean(av.w); }
        As[ak+0][am]=av.x; As[ak+1][am]=av.y; As[ak+2][am]=av.z; As[ak+3][am]=av.w;
        float4 bv;
        if (k0 + bk < K) bv = *(const float4*)(Bb + (size_t)(k0+bk)*N + n0+bn);
        else { bv.x=0.f; bv.y=0.f; bv.z=0.f; bv.w=0.f; }
        Bs[bk][bn+0]=bv.x; Bs[bk][bn+1]=bv.y; Bs[bk][bn+2]=bv.z; Bs[bk][bn+3]=bv.w;
        __syncthreads();
        #pragma unroll
        for (int kk = 0; kk < 8; kk++) {
            float ra[8], rb[8];
            #pragma unroll
            for (int i=0;i<8;i++) ra[i] = As[kk][ty*8+i];
            #pragma unroll
            for (int j=0;j<8;j++) rb[j] = Bs[kk][tx*8+j];
            #pragma unroll
            for (int i=0;i<8;i++) {
                #pragma unroll
                for (int j=0;j<8;j++) acc[i][j] += ra[i]*rb[j];
            }
        }
        __syncthreads();
    }
    #pragma unroll
    for (int i = 0; i < 8; i++) {
        const int row = m0 + ty*8 + i;
        float yval = (EPI==3) ? yv[row] : 0.0f;
        #pragma unroll
        for (int j = 0; j < 8; j++) {
            const int col = n0 + tx*8 + j;
            float v = acc[i][j];
            if (EPI==1) v += biasb[col];
            if (EPI==2) { v += biasb[col]; v = fmaxf(v, 0.0f); }
            if (EPI==3) { v += biasb[col] + yval*yW[col] + yb[col]; }
            Cb[(size_t)row*ldc + col] = v;
        }
    }
}

__global__ __launch_bounds__(256)
void ln_add_kernel(const float* __restrict__ A, const float* __restrict__ B,
                   const float* __restrict__ g, const float* __restrict__ be, float* __restrict__ out){
    __shared__ float red[16];
    const int row = blockIdx.x, tid = threadIdx.x;
    const size_t base = (size_t)row*EMB;
    float x0 = A[base+tid] + B[base+tid];
    float x1 = A[base+tid+256] + B[base+tid+256];
    float s = x0 + x1;
    #pragma unroll
    for (int o=16;o;o>>=1) s += __shfl_down_sync(~0u,s,o);
    if ((tid&31)==0) red[tid>>5]=s;
    __syncthreads();
    if (tid<32){
        float v=(tid<8)?red[tid]:0.f;
        #pragma unroll
        for(int o=4;o;o>>=1) v+=__shfl_down_sync(~0u,v,o);
        if(tid==0) red[8]=v;
    }
    __syncthreads();
    const float mean = red[8]*(1.0f/512.0f);
    const float d0 = x0-mean, d1 = x1-mean;
    float sq = d0*d0 + d1*d1;
    #pragma unroll
    for (int o=16;o;o>>=1) sq += __shfl_down_sync(~0u,sq,o);
    if ((tid&31)==0) red[tid>>5]=sq;
    __syncthreads();
    if (tid<32){
        float v=(tid<8)?red[tid]:0.f;
        #pragma unroll
        for(int o=4;o;o>>=1) v+=__shfl_down_sync(~0u,v,o);
        if(tid==0) red[9]=v;
    }
    __syncthreads();
    const float r = rsqrtf(red[9]*(1.0f/512.0f) + 1e-5f);
    out[base+tid]     = d0*r*g[tid]     + be[tid];
    out[base+tid+256] = d1*r*g[tid+256] + be[tid+256];
}

__global__ void pool_kernel(const float* __restrict__ X, float* __restrict__ P){
    const int b = blockIdx.x, e = threadIdx.x;
    float s = 0.0f;
    for (int t = 0; t < SEP; t++) s += X[((size_t)t*BATCH+b)*EMB + e];
    P[b*EMB+e] = s*(1.0f/(float)SEP);
}

template<int EPI>
__global__ __launch_bounds__(128)
void gemm16_kernel(const float* __restrict__ A, const float* __restrict__ B,
                   const float* __restrict__ bias, float* __restrict__ C, int N, int K){
    __shared__ float As[16][256];
    const int n = blockIdx.x*128 + threadIdx.x;
    float acc[16];
    #pragma unroll
    for (int mm=0;mm<16;mm++) acc[mm]=0.0f;
    for (int k0 = 0; k0 < K; k0 += 256) {
        for (int idx = threadIdx.x; idx < 16*256; idx += 128)
            As[idx>>8][idx&255] = A[(size_t)(idx>>8)*K + k0 + (idx&255)];
        __syncthreads();
        if (n < N) {
            for (int kk = 0; kk < 256; kk += 4) {
                float b0 = B[(size_t)(k0+kk+0)*N+n], b1 = B[(size_t)(k0+kk+1)*N+n];
                float b2 = B[(size_t)(k0+kk+2)*N+n], b3 = B[(size_t)(k0+kk+3)*N+n];
                #pragma unroll
                for (int mm=0;mm<16;mm++){
                    float4 a4 = *(const float4*)&As[mm][kk];
                    acc[mm] += a4.x*b0 + a4.y*b1 + a4.z*b2 + a4.w*b3;
                }
            }
        }
        __syncthreads();
    }
    if (n < N) {
        #pragma unroll
        for (int mm=0;mm<16;mm++){
            float v = acc[mm];
            if (EPI==2){ v += bias[n]; v = fmaxf(v,0.0f); }
            C[(size_t)mm*N+n] = v;
        }
    }
}

__global__ __launch_bounds__(320)
void eval2_kernel(const float* __restrict__ H, const float* __restrict__ W2,
                  const float* __restrict__ B2, float* __restrict__ out){
    __shared__ float hs[32][132];
    __shared__ float w2s[128][10];
    const int b = blockIdx.y, e0 = blockIdx.x*32, tid = threadIdx.x;
    const int i = tid/10, o = tid%10;
    float acc = 0.0f;
    for (int k0 = 0; k0 < HID; k0 += 128) {
        for (int idx = tid; idx < 32*128; idx += 320)
            hs[idx>>7][idx&127] = H[((size_t)(e0+(idx>>7))*BATCH+b)*HID + k0 + (idx&127)];
        for (int idx = tid; idx < 128*10; idx += 320)
            w2s[idx/10][idx%10] = W2[(size_t)b*(HID*NOUT) + (size_t)(k0+idx/10)*NOUT + idx%10];
        __syncthreads();
        #pragma unroll 8
        for (int kk = 0; kk < 128; kk++) acc += hs[i][kk]*w2s[kk][o];
        __syncthreads();
    }
    out[((size_t)(e0+i)*BATCH+b)*NOUT + o] = acc + B2[b*NOUT+o];
}

// ============ host ============
static float* sym(const void* s){ void* p=nullptr; cudaGetSymbolAddress(&p, s); return (float*)p; }
static bf16* symb(const void* s){ void* p=nullptr; cudaGetSymbolAddress(&p, s); return (bf16*)p; }

extern "C" void kernel_launch(void* const* d_in, const int* in_sizes, int n_in,
                              void* d_out, int out_size)
{
    const float *x=(const float*)d_in[0], *y=(const float*)d_in[1];
    const float *enc_W=(const float*)d_in[2], *enc_b=(const float*)d_in[3];
    const float *yenc_W=(const float*)d_in[4], *yenc_b=(const float*)d_in[5];
    const float *Wq=(const float*)d_in[6], *Wk=(const float*)d_in[7];
    const float *Wv=(const float*)d_in[8], *Wo=(const float*)d_in[9];
    const float *ln1_g=(const float*)d_in[10], *ln1_b=(const float*)d_in[11];
    const float *ln2_g=(const float*)d_in[12], *ln2_b=(const float*)d_in[13];
    const float *fW1=(const float*)d_in[14], *fb1=(const float*)d_in[15];
    const float *fW2=(const float*)d_in[16], *fb2=(const float*)d_in[17];
    const float *dec_W=(const float*)d_in[18], *dec_b=(const float*)d_in[19];
    const float *hw1=(const float*)d_in[20], *hb1=(const float*)d_in[21];
    const float *hw2=(const float*)d_in[22], *hb2=(const float*)d_in[23];

    float *bufA=sym(g_bufA), *bufB=sym(g_bufB), *bufC=sym(g_bufC), *bufD=sym(g_bufD);
    bf16 *xh=symb(g_xh), *xl=symb(g_xl);
    bf16 *wqt0=symb(g_wqth), *wqt1=symb(g_wqtl);
    bf16 *wkt0=symb(g_wkth), *wkt1=symb(g_wktl);
    bf16 *wvt0=symb(g_wvth), *wvt1=symb(g_wvtl);
    bf16 *wot0=symb(g_woth), *wot1=symb(g_wotl);
    bf16 *w1t0=symb(g_w1th), *w1t1=symb(g_w1tl);
    bf16 *w2t0=symb(g_w2th), *w2t1=symb(g_w2tl);
    bf16 *qh=symb(g_qh), *ql=symb(g_ql), *kh=symb(g_kh), *kl=symb(g_kl);
    bf16 *vth=symb(g_vth), *vtl=symb(g_vtl);
    float *Smat=sym(g_S);
    bf16 *Ph=symb(g_Ph), *Pl=symb(g_Pl);
    float *oz=sym(g_oz);
    bf16 *aoh=symb(g_aoh), *aol=symb(g_aol);
    bf16 *ffh=symb(g_ffh), *ffl=symb(g_ffl);
    float *pool=sym(g_pool), *dh=sym(g_dh), *w1=sym(g_w1), *b1v=sym(g_b1v), *w2=sym(g_w2), *b2v=sym(g_b2v);
    float *out = (float*)d_out;

    dim3 t328(32,8);
    // 1) encoder (fp32) + split
    sgemm_kernel<3,false><<<dim3(4,128,1),256>>>(x, enc_W, bufA, TROWS, EMB, FEAT, FEAT, EMB,
        enc_b, 0, y, yenc_W, yenc_b, 0,0,0);
    convert_hilo<<<TROWS*EMB/1024,256>>>(bufA, xh, xl);
    // 2) weight transposes + splits
    tconv<<<dim3(16,16),t328>>>(Wq, wqt0, wqt1, EMB, EMB);
    tconv<<<dim3(16,16),t328>>>(Wk, wkt0, wkt1, EMB, EMB);
    tconv<<<dim3(16,16),t328>>>(Wv, wvt0, wvt1, EMB, EMB);
    tconv<<<dim3(16,16),t328>>>(Wo, wot0, wot1, EMB, EMB);
    tconv<<<dim3(64,16),t328>>>(fW1, w1t0, w1t1, EMB, FF);
    tconv<<<dim3(16,64),t328>>>(fW2, w2t0, w2t1, FF, EMB);
    // 3) QKV on tensor pipe
    tc_gemm<128,0,0><<<dim3(4,128,1),256>>>(xh,xl,wqt0,wqt1,bufB,nullptr,nullptr,nullptr,EMB,EMB,0,0,0);
    tc_gemm<128,0,0><<<dim3(4,128,1),256>>>(xh,xl,wkt0,wkt1,bufC,nullptr,nullptr,nullptr,EMB,EMB,0,0,0);
    tc_gemm<128,0,0><<<dim3(4,128,1),256>>>(xh,xl,wvt0,wvt1,bufD,nullptr,nullptr,nullptr,EMB,EMB,0,0,0);
    reshape_qk<<<ZTOT*SEP*64/256,256>>>(bufB, qh, ql, 0.125f);
    reshape_qk<<<ZTOT*SEP*64/256,256>>>(bufC, kh, kl, 1.0f);
    reshape_vT<<<dim3(64,ZTOT),t328>>>(bufD, vth, vtl);
    // 4) S = Q K^T  (per z: M=1024, N=1024, K=64)
    tc_gemm<128,0,0><<<dim3(8,8,ZTOT),256>>>(qh,ql,kh,kl,Smat,nullptr,nullptr,nullptr,
        64, SEP, (long)SEP*64, (long)SEP*64, (long)SEP*SEP);
    softmax_hilo<<<ZTOT*SEP,256>>>(Smat, Ph, Pl);
    // 5) O = P V  (per z: M=1024, N=64, K=1024)
    tc_gemm<64,0,0><<<dim3(1,8,ZTOT),256>>>(Ph,Pl,vth,vtl,oz,nullptr,nullptr,nullptr,
        SEP, 64, (long)SEP*SEP, (long)64*SEP, (long)SEP*64);
    reshape_ao<<<TROWS*EMB/256,256>>>(oz, aoh, aol);
    // 6) Wo
    tc_gemm<128,0,0><<<dim3(4,128,1),256>>>(aoh,aol,wot0,wot1,bufB,nullptr,nullptr,nullptr,EMB,EMB,0,0,0);
    ln_add_kernel<<<TROWS,256>>>(bufB, bufA, ln1_g, ln1_b, bufC);
    convert_hilo<<<TROWS*EMB/1024,256>>>(bufC, xh, xl);
    // 7) FFN
    tc_gemm<128,2,1><<<dim3(16,128,1),256>>>(xh,xl,w1t0,w1t1,nullptr,ffh,ffl,fb1,EMB,FF,0,0,0);
    tc_gemm<128,1,0><<<dim3(4,128,1),256>>>(ffh,ffl,w2t0,w2t1,bufB,nullptr,nullptr,fb2,FF,EMB,0,0,0);
    ln_add_kernel<<<TROWS,256>>>(bufB, bufC, ln2_g, ln2_b, bufD);
    // 8) decoder + heads (fp32)
    pool_kernel<<<BATCH,EMB>>>(bufD, pool);
    gemm16_kernel<2><<<DEC/128,128>>>(pool, dec_W, dec_b, dh, DEC, EMB);
    gemm16_kernel<0><<<(FEAT*HID)/128,128>>>(dh, hw1, nullptr, w1, FEAT*HID, DEC);
    gemm16_kernel<0><<<HID/128,128>>>(dh, hb1, nullptr, b1v, HID, DEC);
    gemm16_kernel<0><<<(HID*NOUT)/128,128>>>(dh, hw2, nullptr, w2, HID*NOUT, DEC);
    gemm16_kernel<0><<<1,128>>>(dh, hb2, nullptr, b2v, NOUT, DEC);
    // 9) eval MLP (fp32)
    sgemm_kernel<2,true><<<dim3(4,8,BATCH),256>>>(
        x + (size_t)SEP*BATCH*FEAT, w1, bufA, S_TOT-SEP, HID, FEAT, BATCH*FEAT, BATCH*HID,
        b1v, HID, nullptr, nullptr, nullptr, (long)FEAT, (long)FEAT*HID, (long)HID);
    eval2_kernel<<<dim3((S_TOT-SEP)/32,BATCH),320>>>(bufA, w2, b2v, out);
}